// round 5
// baseline (speedup 1.0000x reference)
#include <cuda_runtime.h>
#include <cstdint>

// Problem constants
constexpr int BB = 32;       // batch
constexpr int TT = 2048;     // time steps

// ---------------- scratch (static device globals; no allocation allowed) ----
__device__ float g_xg[(size_t)BB * TT * 3072];     // input-gate projections, max 3H=3072
__device__ float g_act0[(size_t)BB * TT * 1024];   // activation ping
__device__ float g_act1[(size_t)BB * TT * 1024];   // activation pong
__device__ float g_h[2 * 32 * 1024];               // hidden state, double buffered, layout f4[k>>2][b][k&3]
__device__ unsigned g_cnt;                          // grid barrier counter
__device__ unsigned g_gen;                          // grid barrier generation

// ---------------- packed f32x2 helpers (sm_100+) ---------------------------
__device__ __forceinline__ void fma2(unsigned long long& a, unsigned long long x, unsigned long long y) {
    asm("fma.rn.f32x2 %0, %1, %2, %0;" : "+l"(a) : "l"(x), "l"(y));
}
__device__ __forceinline__ unsigned long long pk2(float x, float y) {
    unsigned long long r; asm("mov.b64 %0, {%1,%2};" : "=l"(r) : "f"(x), "f"(y)); return r;
}
__device__ __forceinline__ float2 up2(unsigned long long v) {
    float2 f; asm("mov.b64 {%0,%1}, %2;" : "=f"(f.x), "=f"(f.y) : "l"(v)); return f;
}

union HU { float4 f; ulonglong2 u; };

__device__ __forceinline__ void cpa16(void* dst, const void* src) {
    uint32_t d = (uint32_t)__cvta_generic_to_shared(dst);
    asm volatile("cp.async.cg.shared.global [%0], [%1], 16;" :: "r"(d), "l"(src));
}

// ---------------- input projection GEMM -------------------------------------
// C[m, n] = sum_k A[m, k] * W[n, k] + bias[n],  m = b*TT + t
// Tile: BM=128, BN=128, BK=16; 256 threads; per-thread 8 rows x 8 cols via
// f32x2 row pairs (32 fma2 per k). Register-staged pipelining: LDG next
// K-block while computing current SMEM tile, STS afterwards.
__global__ __launch_bounds__(256, 2) void gemm_xg(
    const float* __restrict__ A, const float* __restrict__ W,
    const float* __restrict__ bias, float* __restrict__ C,
    int K, int N3, long sb, long st, long sk)
{
    __shared__ __align__(16) float As[16][128];
    __shared__ __align__(16) float Bs[16][128];

    int tid = threadIdx.x;
    int n0 = blockIdx.x * 128;
    int m0 = blockIdx.y * 128;
    int bidx = m0 / TT;
    int t0 = m0 % TT;          // TT % 128 == 0 so tile stays within one batch row
    const float* Ab = A + (size_t)bidx * sb + (size_t)t0 * st;
    int tx = tid & 15, ty = tid >> 4;

    unsigned long long acc[4][8];
#pragma unroll
    for (int p = 0; p < 4; ++p)
#pragma unroll
        for (int j = 0; j < 8; ++j) acc[p][j] = 0ull;

    float4 ra[2], rb[2];

    // ---- load K-block k0 into registers ----
    auto load_regs = [&](int k0) {
        if (sk == 1) {
#pragma unroll
            for (int i = 0; i < 2; ++i) {
                int lin = tid + i * 256;
                int m = lin >> 2, kq = (lin & 3) * 4;
                ra[i] = *(const float4*)(Ab + (size_t)m * st + (k0 + kq));
            }
        } else {
#pragma unroll
            for (int i = 0; i < 2; ++i) {
                int lin = tid + i * 256;
                int k = lin >> 5, m4 = (lin & 31) * 4;
                ra[i] = *(const float4*)(Ab + m4 + (size_t)(k0 + k) * sk);
            }
        }
#pragma unroll
        for (int i = 0; i < 2; ++i) {
            int lin = tid + i * 256;
            int n = lin >> 2, kq = (lin & 3) * 4;
            rb[i] = *(const float4*)&W[(size_t)(n0 + n) * K + k0 + kq];
        }
    };

    // ---- store registers into SMEM tile ----
    auto store_smem = [&]() {
        if (sk == 1) {
#pragma unroll
            for (int i = 0; i < 2; ++i) {
                int lin = tid + i * 256;
                int m = lin >> 2, kq = (lin & 3) * 4;
                As[kq + 0][m] = ra[i].x; As[kq + 1][m] = ra[i].y;
                As[kq + 2][m] = ra[i].z; As[kq + 3][m] = ra[i].w;
            }
        } else {
#pragma unroll
            for (int i = 0; i < 2; ++i) {
                int lin = tid + i * 256;
                int k = lin >> 5, m4 = (lin & 31) * 4;
                *(float4*)&As[k][m4] = ra[i];
            }
        }
#pragma unroll
        for (int i = 0; i < 2; ++i) {
            int lin = tid + i * 256;
            int n = lin >> 2, kq = (lin & 3) * 4;
            Bs[kq + 0][n] = rb[i].x; Bs[kq + 1][n] = rb[i].y;
            Bs[kq + 2][n] = rb[i].z; Bs[kq + 3][n] = rb[i].w;
        }
    };

    load_regs(0);
    store_smem();
    __syncthreads();

    for (int k0 = 0; k0 < K; k0 += 16) {
        bool last = (k0 + 16 >= K);
        if (!last) load_regs(k0 + 16);     // prefetch next block (hidden under FMAs)

#pragma unroll
        for (int k = 0; k < 16; ++k) {
            const ulonglong2* ap = (const ulonglong2*)&As[k][ty * 8];
            ulonglong2 A0 = ap[0], A1 = ap[1];
            unsigned long long am[4] = {A0.x, A0.y, A1.x, A1.y};
            float4 b0 = *(const float4*)&Bs[k][tx * 8];
            float4 b1 = *(const float4*)&Bs[k][tx * 8 + 4];
            unsigned long long bd[8] = {pk2(b0.x, b0.x), pk2(b0.y, b0.y),
                                        pk2(b0.z, b0.z), pk2(b0.w, b0.w),
                                        pk2(b1.x, b1.x), pk2(b1.y, b1.y),
                                        pk2(b1.z, b1.z), pk2(b1.w, b1.w)};
#pragma unroll
            for (int p = 0; p < 4; ++p)
#pragma unroll
                for (int j = 0; j < 8; ++j) fma2(acc[p][j], am[p], bd[j]);
        }
        __syncthreads();
        if (!last) {
            store_smem();
            __syncthreads();
        }
    }

    float4 bv0 = *(const float4*)&bias[n0 + tx * 8];
    float4 bv1 = *(const float4*)&bias[n0 + tx * 8 + 4];
#pragma unroll
    for (int p = 0; p < 4; ++p) {
        float2 c[8];
#pragma unroll
        for (int j = 0; j < 8; ++j) c[j] = up2(acc[p][j]);
        size_t r0 = (size_t)(m0 + ty * 8 + 2 * p) * N3 + n0 + tx * 8;
        float4 lo0 = {c[0].x + bv0.x, c[1].x + bv0.y, c[2].x + bv0.z, c[3].x + bv0.w};
        float4 hi0 = {c[4].x + bv1.x, c[5].x + bv1.y, c[6].x + bv1.z, c[7].x + bv1.w};
        float4 lo1 = {c[0].y + bv0.x, c[1].y + bv0.y, c[2].y + bv0.z, c[3].y + bv0.w};
        float4 hi1 = {c[4].y + bv1.x, c[5].y + bv1.y, c[6].y + bv1.z, c[7].y + bv1.w};
        *(float4*)&C[r0] = lo0;
        *(float4*)&C[r0 + 4] = hi0;
        *(float4*)&C[r0 + N3] = lo1;
        *(float4*)&C[r0 + N3 + 4] = hi1;
    }
}

// ---------------- zero hidden state ----------------------------------------
__global__ void zero_h_kernel() {
    int i = blockIdx.x * blockDim.x + threadIdx.x;
    if (i < 2 * 32 * 1024) g_h[i] = 0.f;
}

// ---------------- persistent GRU recurrence (unchanged from round 4) --------
template<int K, int HC>
__global__ __launch_bounds__(256) void recur_kernel(
    const float* __restrict__ xg, const float* __restrict__ w_hh,
    const float* __restrict__ b_hh, float* __restrict__ out,
    long os_b, long os_t, long os_j)
{
    constexpr int NR = 3 * HC;
    constexpr int H = K;
    constexpr int k4n = (K / 4) / 8;          // float4 k-groups per warp
    constexpr int CW = 8;                     // k-groups per chunk
    constexpr int NC = k4n / CW;              // chunks per warp
    extern __shared__ __align__(16) float smem[];
    float* w_s = smem;                                   // [NR][K]
    float4* hb4 = (float4*)(smem + NR * K);              // [8 warps][2 bufs][CW*32] float4
    float* red = smem + NR * K + 8 * 2 * CW * 32 * 4;    // [8][NR][32]

    int tid = threadIdx.x;
    int cta = blockIdx.x;
    int G = gridDim.x;
    int j0 = cta * HC;

    for (int r = 0; r < NR; ++r) {
        int gate = r / HC, jl = r % HC;
        int j = j0 + jl;
        for (int k = tid * 4; k < K; k += 1024) {
            float4 v = make_float4(0.f, 0.f, 0.f, 0.f);
            if (j < H) v = *(const float4*)&w_hh[(size_t)(gate * H + j) * K + k];
            *(float4*)&w_s[r * K + k] = v;
        }
    }
    unsigned local_gen = 0;
    if (tid == 0) local_gen = *(volatile unsigned*)&g_gen;
    __syncthreads();

    int warp = tid >> 5, lane = tid & 31;
    int k4b = warp * k4n;
    float4* mybuf = hb4 + warp * 2 * CW * 32;
    const float* wcol0 = w_s + k4b * 4;

    int ejl = tid >> 5, eb = tid & 31;
    int jg = j0 + ejl;
    bool epi = (tid < HC * 32) && (jg < H);
    int hidx = (jg >> 2) * 128 + eb * 4 + (jg & 3);
    const float* xgbase = xg + (size_t)eb * TT * (3 * H) + jg;
    float bh0 = 0.f, bh1 = 0.f, bh2 = 0.f;
    if (epi) { bh0 = b_hh[jg]; bh1 = b_hh[H + jg]; bh2 = b_hh[2 * H + jg]; }
    float hreg = 0.f;

    for (int t = 0; t < TT; ++t) {
        int p = t & 1;
        const float4* hp = (const float4*)&g_h[p * 32 * 1024] + (size_t)k4b * 32;

#pragma unroll
        for (int c0 = 0; c0 < 2 && c0 < NC; ++c0) {
            float4* dst = mybuf + c0 * CW * 32;
            const float4* src = hp + c0 * CW * 32;
#pragma unroll
            for (int kk = 0; kk < CW; ++kk)
                cpa16(dst + kk * 32 + lane, src + kk * 32 + lane);
            asm volatile("cp.async.commit_group;" ::: "memory");
        }

        float xr = 0.f, xz = 0.f, xn = 0.f;
        if (epi) {
            const float* xp = xgbase + (size_t)t * (3 * H);
            xr = __ldcs(xp); xz = __ldcs(xp + H); xn = __ldcs(xp + 2 * H);
        }

        unsigned long long acc[NR];
#pragma unroll
        for (int r = 0; r < NR; ++r) acc[r] = 0ull;

#pragma unroll
        for (int c = 0; c < NC; ++c) {
            if (c + 1 < NC) asm volatile("cp.async.wait_group 1;" ::: "memory");
            else            asm volatile("cp.async.wait_group 0;" ::: "memory");
            const float4* buf = mybuf + (c & 1) * CW * 32;
            const float* wc = wcol0 + c * CW * 4;
#pragma unroll
            for (int kk = 0; kk < CW; ++kk) {
                HU hv; hv.f = buf[kk * 32 + lane];
#pragma unroll
                for (int r = 0; r < NR; ++r) {
                    ulonglong2 wv = *(const ulonglong2*)&wc[r * K + kk * 4];
                    fma2(acc[r], hv.u.x, wv.x);
                    fma2(acc[r], hv.u.y, wv.y);
                }
            }
            if (c + 2 < NC) {
                float4* dst = mybuf + (c & 1) * CW * 32;
                const float4* src = hp + (c + 2) * CW * 32;
#pragma unroll
                for (int kk = 0; kk < CW; ++kk)
                    cpa16(dst + kk * 32 + lane, src + kk * 32 + lane);
                asm volatile("cp.async.commit_group;" ::: "memory");
            }
        }

#pragma unroll
        for (int r = 0; r < NR; ++r) {
            float2 f = up2(acc[r]);
            red[(warp * NR + r) * 32 + lane] = f.x + f.y;
        }
        __syncthreads();

        if (epi) {
            float s[3];
#pragma unroll
            for (int gate = 0; gate < 3; ++gate) {
                float v = (gate == 0) ? bh0 : (gate == 1) ? bh1 : bh2;
#pragma unroll
                for (int w = 0; w < 8; ++w)
                    v += red[(w * NR + gate * HC + ejl) * 32 + eb];
                s[gate] = v;
            }
            float r_ = 1.f / (1.f + __expf(-(xr + s[0])));
            float z_ = 1.f / (1.f + __expf(-(xz + s[1])));
            float n_ = tanhf(xn + r_ * s[2]);
            float hnew = (1.f - z_) * n_ + z_ * hreg;
            hreg = hnew;
            g_h[(p ^ 1) * 32 * 1024 + hidx] = hnew;
            __stcs(&out[(size_t)eb * os_b + (size_t)t * os_t + (size_t)jg * os_j], hnew);
            __threadfence();
        }

        __syncthreads();
        if (tid == 0) {
            unsigned a = atomicAdd(&g_cnt, 1);
            if (a == (unsigned)G - 1) {
                g_cnt = 0;
                __threadfence();
                atomicAdd(&g_gen, 1);
            } else {
                while (*(volatile unsigned*)&g_gen == local_gen) { }
            }
            local_gen++;
        }
        __syncthreads();
    }
}

extern "C" void kernel_launch(void* const* d_in, const int* in_sizes, int n_in,
                              void* d_out, int out_size) {
    const float* x = (const float*)d_in[0];
    const float* wih[4]; const float* whh[4]; const float* bih[4]; const float* bhh[4];
    for (int l = 0; l < 4; ++l) {
        wih[l] = (const float*)d_in[1 + 4 * l];
        whh[l] = (const float*)d_in[2 + 4 * l];
        bih[l] = (const float*)d_in[3 + 4 * l];
        bhh[l] = (const float*)d_in[4 + 4 * l];
    }
    float *xg, *a0, *a1;
    cudaGetSymbolAddress((void**)&xg, g_xg);
    cudaGetSymbolAddress((void**)&a0, g_act0);
    cudaGetSymbolAddress((void**)&a1, g_act1);
    float* dout = (float*)d_out;

    const int SMEM4 = (3 * 4 * 512) * 4 + 65536 + (8 * 12 * 32) * 4;    // 102400 B
    const int SMEM7 = (3 * 7 * 1024) * 4 + 65536 + (8 * 21 * 32) * 4;   // 173056 B
    cudaFuncSetAttribute(recur_kernel<512, 4>, cudaFuncAttributeMaxDynamicSharedMemorySize, SMEM4);
    cudaFuncSetAttribute(recur_kernel<1024, 7>, cudaFuncAttributeMaxDynamicSharedMemorySize, SMEM7);

    struct Cfg { const float* A; int K; int H; long sb, st, sk; float* out; long ob, ot, oj; };
    Cfg cfg[4] = {
        { x,   256,  512, (long)256 * 2048,  1,    2048, a0,   (long)2048 * 512,  512,  1    },
        { a0,  512,  512, (long)2048 * 512,  512,  1,    a1,   (long)2048 * 512,  512,  1    },
        { a1,  512, 1024, (long)2048 * 512,  512,  1,    a0,   (long)2048 * 1024, 1024, 1    },
        { a0, 1024, 1024, (long)2048 * 1024, 1024, 1,    dout, (long)1024 * 2048, 1,    2048 },
    };

    for (int l = 0; l < 4; ++l) {
        int N3 = 3 * cfg[l].H;
        dim3 gg(N3 / 128, (BB * TT) / 128);
        gemm_xg<<<gg, 256>>>(cfg[l].A, wih[l], bih[l], xg,
                             cfg[l].K, N3, cfg[l].sb, cfg[l].st, cfg[l].sk);
        zero_h_kernel<<<64, 1024>>>();
        if (cfg[l].H == 512)
            recur_kernel<512, 4><<<128, 256, SMEM4>>>(xg, whh[l], bhh[l], cfg[l].out,
                                                      cfg[l].ob, cfg[l].ot, cfg[l].oj);
        else
            recur_kernel<1024, 7><<<147, 256, SMEM7>>>(xg, whh[l], bhh[l], cfg[l].out,
                                                       cfg[l].ob, cfg[l].ot, cfg[l].oj);
    }
}